// round 4
// baseline (speedup 1.0000x reference)
#include <cuda_runtime.h>

#define NN 50000
#define DD 128
#define EE 800000

// Scratch (__device__ globals; no allocations allowed)
__device__ float g_h   [NN * DD];   // GEMM output
__device__ float g_z   [NN * DD];   // layer-1 activation
__device__ float g_agg [NN * DD];   // aggregation accumulator
__device__ float g_dinv[NN];        // degree -> d^{-1/2}
__device__ int   g_src [EE];        // converted int32 src
__device__ int   g_dst [EE];        // converted int32 dst
__device__ float g_norm[EE];        // per-edge normalization
__device__ int   g_is64;            // edge_index dtype flag

// -------- dtype detection: int64 iff odd 32-bit words are all zero --------
__global__ void k_detect(const int* __restrict__ ei32) {
    if (threadIdx.x == 0 && blockIdx.x == 0) {
        int acc = 0;
#pragma unroll
        for (int i = 0; i < 64; ++i) acc |= ei32[2 * i + 1];
        g_is64 = (acc == 0) ? 1 : 0;
    }
}

// -------- convert edge_index to int32 src/dst --------
__global__ void k_convert(const int* __restrict__ ei32, int E) {
    int e = blockIdx.x * blockDim.x + threadIdx.x;
    if (e >= E) return;
    int s, d;
    if (g_is64) {              // int64 little-endian: take low words
        s = ei32[2 * e];
        d = ei32[2 * (E + e)];
    } else {                   // already int32
        s = ei32[e];
        d = ei32[E + e];
    }
    g_src[e] = s;
    g_dst[e] = d;
}

// -------- degree / normalization --------
__global__ void k_init_deg(int n) {
    int i = blockIdx.x * blockDim.x + threadIdx.x;
    if (i < n) g_dinv[i] = 1.0f;   // self-loop weight
}

__global__ void k_deg(const float* __restrict__ ew, int E) {
    int e = blockIdx.x * blockDim.x + threadIdx.x;
    if (e < E) atomicAdd(&g_dinv[g_dst[e]], ew[e]);
}

__global__ void k_finalize_deg(int n) {
    int i = blockIdx.x * blockDim.x + threadIdx.x;
    if (i < n) {
        float deg = g_dinv[i];
        g_dinv[i] = (deg > 0.0f) ? rsqrtf(deg) : 0.0f;
    }
}

__global__ void k_norm(const float* __restrict__ ew, int E) {
    int e = blockIdx.x * blockDim.x + threadIdx.x;
    if (e < E) g_norm[e] = g_dinv[g_src[e]] * ew[e] * g_dinv[g_dst[e]];
}

// -------- tiled GEMM: g_h = X @ W, 64 rows x 128 cols per block --------
// blockDim = 256: tx = tid%32 (4 cols each), ty = tid/32 (8 rows each)
__global__ void k_gemm(const float* __restrict__ Xext,
                       const float* __restrict__ W,
                       int use_gz, int N) {
    __shared__ float xs[16][65];     // [k][row], padded
    __shared__ float ws[16][128];    // [k][col]

    const float* __restrict__ X = use_gz ? g_z : Xext;
    int tid = threadIdx.x;
    int tx = tid & 31;
    int ty = tid >> 5;
    int r0 = blockIdx.x * 64;

    float4 acc[8];
#pragma unroll
    for (int r = 0; r < 8; ++r) acc[r] = make_float4(0.f, 0.f, 0.f, 0.f);

    for (int k0 = 0; k0 < DD; k0 += 16) {
        // load X tile (64 rows x 16 k) -> xs[k][row]
        {
            int row = tid >> 2;            // 0..63
            int q   = tid & 3;             // 0..3 (quad of k)
            float4 v = make_float4(0.f, 0.f, 0.f, 0.f);
            if (r0 + row < N)
                v = *(const float4*)&X[(r0 + row) * DD + k0 + q * 4];
            xs[q * 4 + 0][row] = v.x;
            xs[q * 4 + 1][row] = v.y;
            xs[q * 4 + 2][row] = v.z;
            xs[q * 4 + 3][row] = v.w;
        }
        // load W tile (16 k x 128 cols) -> ws
        {
#pragma unroll
            for (int rep = 0; rep < 2; ++rep) {
                int f  = tid + rep * 256;  // 0..511 quads
                int kk = f >> 5;           // 0..15
                int c4 = f & 31;           // 0..31
                *(float4*)&ws[kk][c4 * 4] =
                    *(const float4*)&W[(k0 + kk) * DD + c4 * 4];
            }
        }
        __syncthreads();

#pragma unroll
        for (int kk = 0; kk < 16; ++kk) {
            float4 w = *(float4*)&ws[kk][tx * 4];
#pragma unroll
            for (int r = 0; r < 8; ++r) {
                float xv = xs[kk][ty * 8 + r];
                acc[r].x = fmaf(xv, w.x, acc[r].x);
                acc[r].y = fmaf(xv, w.y, acc[r].y);
                acc[r].z = fmaf(xv, w.z, acc[r].z);
                acc[r].w = fmaf(xv, w.w, acc[r].w);
            }
        }
        __syncthreads();
    }

#pragma unroll
    for (int r = 0; r < 8; ++r) {
        int row = r0 + ty * 8 + r;
        if (row < N)
            *(float4*)&g_h[row * DD + tx * 4] = acc[r];
    }
}

// -------- init agg with self-loop + bias: agg = dinv^2 * h + b --------
__global__ void k_init_agg(const float* __restrict__ b, int N) {
    int i = blockIdx.x * blockDim.x + threadIdx.x;   // float4 index
    int total = N * 32;
    if (i >= total) return;
    int node = i >> 5;
    int j4   = i & 31;
    float di = g_dinv[node];
    float di2 = di * di;
    float4 h = ((const float4*)g_h)[i];
    float4 bb = ((const float4*)b)[j4];
    float4 v;
    v.x = fmaf(di2, h.x, bb.x);
    v.y = fmaf(di2, h.y, bb.y);
    v.z = fmaf(di2, h.z, bb.z);
    v.w = fmaf(di2, h.w, bb.w);
    ((float4*)g_agg)[i] = v;
}

// -------- edge scatter: warp per edge, float4 gather, scalar atomics --------
__global__ void k_scatter(int E) {
    int gw   = (blockIdx.x * blockDim.x + threadIdx.x) >> 5;
    int lane = threadIdx.x & 31;
    if (gw >= E) return;
    int s = g_src[gw];
    int d = g_dst[gw];
    float nrm = g_norm[gw];
    float4 v = ((const float4*)g_h)[s * 32 + lane];
    float* dst = &g_agg[d * DD + lane * 4];
    atomicAdd(dst + 0, nrm * v.x);
    atomicAdd(dst + 1, nrm * v.y);
    atomicAdd(dst + 2, nrm * v.z);
    atomicAdd(dst + 3, nrm * v.w);
}

// -------- epilogue: PReLU, write to g_z or external out --------
__global__ void k_epilogue(const float* __restrict__ a,
                           float* __restrict__ Oext, int use_ext, int N) {
    float* Z = use_ext ? Oext : g_z;
    int i = blockIdx.x * blockDim.x + threadIdx.x;   // float4 index
    int total = N * 32;
    if (i >= total) return;
    int j4 = i & 31;
    float4 v  = ((const float4*)g_agg)[i];
    float4 aa = ((const float4*)a)[j4];
    v.x = (v.x > 0.f) ? v.x : aa.x * v.x;
    v.y = (v.y > 0.f) ? v.y : aa.y * v.y;
    v.z = (v.z > 0.f) ? v.z : aa.z * v.z;
    v.w = (v.w > 0.f) ? v.w : aa.w * v.w;
    ((float4*)Z)[i] = v;
}

// -------- launch --------
extern "C" void kernel_launch(void* const* d_in, const int* in_sizes, int n_in,
                              void* d_out, int out_size) {
    const float* x  = (const float*)d_in[0];
    const int*   ei = (const int*)d_in[1];   // int32 view; dtype detected on device
    const float* ew = (const float*)d_in[2];
    const float* W1 = (const float*)d_in[3];
    const float* b1 = (const float*)d_in[4];
    const float* a1 = (const float*)d_in[5];
    const float* W2 = (const float*)d_in[6];
    const float* b2 = (const float*)d_in[7];
    const float* a2 = (const float*)d_in[8];
    float* out = (float*)d_out;

    const int N = in_sizes[0] / DD;   // 50000
    const int E = in_sizes[2];        // 800000

    // edge preprocessing (once per call, reused by both layers)
    k_detect<<<1, 32>>>(ei);
    k_convert<<<(E + 255) / 256, 256>>>(ei, E);
    k_init_deg<<<(N + 255) / 256, 256>>>(N);
    k_deg<<<(E + 255) / 256, 256>>>(ew, E);
    k_finalize_deg<<<(N + 255) / 256, 256>>>(N);
    k_norm<<<(E + 255) / 256, 256>>>(ew, E);

    const int gemm_grid = (N + 63) / 64;           // 782
    const int vec_grid  = (N * 32 + 255) / 256;    // 6250
    const int sc_grid   = (E * 32 + 255) / 256;    // 100000 (warp per edge)

    // ---- layer 1 ----
    k_gemm<<<gemm_grid, 256>>>(x, W1, 0, N);
    k_init_agg<<<vec_grid, 256>>>(b1, N);
    k_scatter<<<sc_grid, 256>>>(E);
    k_epilogue<<<vec_grid, 256>>>(a1, out, 0, N);

    // ---- layer 2 ----
    k_gemm<<<gemm_grid, 256>>>(nullptr, W2, 1, N);
    k_init_agg<<<vec_grid, 256>>>(b2, N);
    k_scatter<<<sc_grid, 256>>>(E);
    k_epilogue<<<vec_grid, 256>>>(a2, out, 1, N);
}

// round 5
// speedup vs baseline: 2.2528x; 2.2528x over previous
#include <cuda_runtime.h>

#define NN 50000
#define DD 128
#define EE 800000

// Scratch (__device__ globals; no allocations allowed)
__device__ float g_h    [NN * DD];   // GEMM output
__device__ float g_z    [NN * DD];   // layer-1 activation
__device__ float g_dinv [NN];        // weighted degree -> d^{-1/2}
__device__ int   g_cnt  [NN];        // in-degree counts (unweighted)
__device__ int   g_rowptr[NN + 1];   // CSR row pointers (by dst)
__device__ int   g_cursor[NN];       // placement cursors
__device__ int   g_src  [EE];        // int32 src
__device__ int   g_dst  [EE];        // int32 dst
__device__ int   g_esrc [EE];        // CSR-ordered src
__device__ float g_enorm[EE];        // CSR-ordered edge norm
__device__ int   g_is64;             // edge_index dtype flag

// -------- dtype detection: int64 iff odd 32-bit words are all zero --------
__global__ void k_detect(const int* __restrict__ ei32) {
    if (threadIdx.x == 0 && blockIdx.x == 0) {
        int acc = 0;
#pragma unroll
        for (int i = 0; i < 64; ++i) acc |= ei32[2 * i + 1];
        g_is64 = (acc == 0) ? 1 : 0;
    }
}

// -------- init per-node state --------
__global__ void k_init_node(int n) {
    int i = blockIdx.x * blockDim.x + threadIdx.x;
    if (i < n) {
        g_dinv[i] = 1.0f;   // self-loop weight
        g_cnt[i]  = 0;
    }
}

// -------- convert indices + weighted degree + count histogram --------
__global__ void k_convert(const int* __restrict__ ei32,
                          const float* __restrict__ ew, int E) {
    int e = blockIdx.x * blockDim.x + threadIdx.x;
    if (e >= E) return;
    int s, d;
    if (g_is64) {              // int64 little-endian: low words
        s = ei32[2 * e];
        d = ei32[2 * (E + e)];
    } else {
        s = ei32[e];
        d = ei32[E + e];
    }
    g_src[e] = s;
    g_dst[e] = d;
    atomicAdd(&g_dinv[d], ew[e]);
    atomicAdd(&g_cnt[d], 1);
}

__global__ void k_finalize_deg(int n) {
    int i = blockIdx.x * blockDim.x + threadIdx.x;
    if (i < n) {
        float deg = g_dinv[i];
        g_dinv[i] = (deg > 0.0f) ? rsqrtf(deg) : 0.0f;
    }
}

// -------- single-block exclusive scan of g_cnt -> g_rowptr / g_cursor --------
__global__ void k_scan(int N) {
    __shared__ int sh[1024];
    __shared__ int carry;
    int tid = threadIdx.x;
    if (tid == 0) carry = 0;
    __syncthreads();
    for (int base = 0; base < N; base += 1024) {
        int i = base + tid;
        int v = (i < N) ? g_cnt[i] : 0;
        sh[tid] = v;
        __syncthreads();
#pragma unroll
        for (int off = 1; off < 1024; off <<= 1) {
            int t = (tid >= off) ? sh[tid - off] : 0;
            __syncthreads();
            sh[tid] += t;
            __syncthreads();
        }
        int excl = sh[tid] - v;
        int c = carry;
        if (i < N) {
            g_rowptr[i] = c + excl;
            g_cursor[i] = c + excl;
        }
        __syncthreads();
        if (tid == 0) carry = c + sh[1023];
        __syncthreads();
    }
    if (tid == 0) g_rowptr[N] = carry;
}

// -------- place edges into CSR order, compute per-edge norm --------
__global__ void k_place(const float* __restrict__ ew, int E) {
    int e = blockIdx.x * blockDim.x + threadIdx.x;
    if (e >= E) return;
    int s = g_src[e];
    int d = g_dst[e];
    int pos = atomicAdd(&g_cursor[d], 1);
    g_esrc[pos]  = s;
    g_enorm[pos] = g_dinv[s] * ew[e] * g_dinv[d];
}

// -------- tiled GEMM: g_h = X @ W, 64 rows x 128 cols per block --------
__global__ void k_gemm(const float* __restrict__ Xext,
                       const float* __restrict__ W,
                       int use_gz, int N) {
    __shared__ float xs[16][65];
    __shared__ float ws[16][128];

    const float* __restrict__ X = use_gz ? g_z : Xext;
    int tid = threadIdx.x;
    int tx = tid & 31;
    int ty = tid >> 5;
    int r0 = blockIdx.x * 64;

    float4 acc[8];
#pragma unroll
    for (int r = 0; r < 8; ++r) acc[r] = make_float4(0.f, 0.f, 0.f, 0.f);

    for (int k0 = 0; k0 < DD; k0 += 16) {
        {
            int row = tid >> 2;
            int q   = tid & 3;
            float4 v = make_float4(0.f, 0.f, 0.f, 0.f);
            if (r0 + row < N)
                v = *(const float4*)&X[(r0 + row) * DD + k0 + q * 4];
            xs[q * 4 + 0][row] = v.x;
            xs[q * 4 + 1][row] = v.y;
            xs[q * 4 + 2][row] = v.z;
            xs[q * 4 + 3][row] = v.w;
        }
        {
#pragma unroll
            for (int rep = 0; rep < 2; ++rep) {
                int f  = tid + rep * 256;
                int kk = f >> 5;
                int c4 = f & 31;
                *(float4*)&ws[kk][c4 * 4] =
                    *(const float4*)&W[(k0 + kk) * DD + c4 * 4];
            }
        }
        __syncthreads();

#pragma unroll
        for (int kk = 0; kk < 16; ++kk) {
            float4 w = *(float4*)&ws[kk][tx * 4];
#pragma unroll
            for (int r = 0; r < 8; ++r) {
                float xv = xs[kk][ty * 8 + r];
                acc[r].x = fmaf(xv, w.x, acc[r].x);
                acc[r].y = fmaf(xv, w.y, acc[r].y);
                acc[r].z = fmaf(xv, w.z, acc[r].z);
                acc[r].w = fmaf(xv, w.w, acc[r].w);
            }
        }
        __syncthreads();
    }

#pragma unroll
    for (int r = 0; r < 8; ++r) {
        int row = r0 + ty * 8 + r;
        if (row < N)
            *(float4*)&g_h[row * DD + tx * 4] = acc[r];
    }
}

// -------- fused aggregate: warp per node; gather + self-loop + bias + PReLU --------
__global__ void k_aggregate(const float* __restrict__ b,
                            const float* __restrict__ a,
                            float* __restrict__ Oext, int use_ext, int N) {
    int node = (blockIdx.x * blockDim.x + threadIdx.x) >> 5;
    if (node >= N) return;
    int lane = threadIdx.x & 31;

    const float4* __restrict__ h4 = (const float4*)g_h;
    float di  = g_dinv[node];
    float di2 = di * di;

    float4 hv = h4[node * 32 + lane];
    float4 bb = ((const float4*)b)[lane];
    float4 acc;
    acc.x = fmaf(di2, hv.x, bb.x);
    acc.y = fmaf(di2, hv.y, bb.y);
    acc.z = fmaf(di2, hv.z, bb.z);
    acc.w = fmaf(di2, hv.w, bb.w);

    int i   = g_rowptr[node];
    int end = g_rowptr[node + 1];

    for (; i + 4 <= end; i += 4) {
        int   s0 = g_esrc[i],     s1 = g_esrc[i + 1];
        int   s2 = g_esrc[i + 2], s3 = g_esrc[i + 3];
        float w0 = g_enorm[i],     w1 = g_enorm[i + 1];
        float w2 = g_enorm[i + 2], w3 = g_enorm[i + 3];
        float4 v0 = h4[s0 * 32 + lane];
        float4 v1 = h4[s1 * 32 + lane];
        float4 v2 = h4[s2 * 32 + lane];
        float4 v3 = h4[s3 * 32 + lane];
        acc.x = fmaf(w0, v0.x, acc.x); acc.y = fmaf(w0, v0.y, acc.y);
        acc.z = fmaf(w0, v0.z, acc.z); acc.w = fmaf(w0, v0.w, acc.w);
        acc.x = fmaf(w1, v1.x, acc.x); acc.y = fmaf(w1, v1.y, acc.y);
        acc.z = fmaf(w1, v1.z, acc.z); acc.w = fmaf(w1, v1.w, acc.w);
        acc.x = fmaf(w2, v2.x, acc.x); acc.y = fmaf(w2, v2.y, acc.y);
        acc.z = fmaf(w2, v2.z, acc.z); acc.w = fmaf(w2, v2.w, acc.w);
        acc.x = fmaf(w3, v3.x, acc.x); acc.y = fmaf(w3, v3.y, acc.y);
        acc.z = fmaf(w3, v3.z, acc.z); acc.w = fmaf(w3, v3.w, acc.w);
    }
    for (; i < end; ++i) {
        int   s = g_esrc[i];
        float w = g_enorm[i];
        float4 v = h4[s * 32 + lane];
        acc.x = fmaf(w, v.x, acc.x); acc.y = fmaf(w, v.y, acc.y);
        acc.z = fmaf(w, v.z, acc.z); acc.w = fmaf(w, v.w, acc.w);
    }

    float4 aa = ((const float4*)a)[lane];
    acc.x = (acc.x > 0.f) ? acc.x : aa.x * acc.x;
    acc.y = (acc.y > 0.f) ? acc.y : aa.y * acc.y;
    acc.z = (acc.z > 0.f) ? acc.z : aa.z * acc.z;
    acc.w = (acc.w > 0.f) ? acc.w : aa.w * acc.w;

    float4* Z = use_ext ? (float4*)Oext : (float4*)g_z;
    Z[node * 32 + lane] = acc;
}

// -------- launch --------
extern "C" void kernel_launch(void* const* d_in, const int* in_sizes, int n_in,
                              void* d_out, int out_size) {
    const float* x  = (const float*)d_in[0];
    const int*   ei = (const int*)d_in[1];
    const float* ew = (const float*)d_in[2];
    const float* W1 = (const float*)d_in[3];
    const float* b1 = (const float*)d_in[4];
    const float* a1 = (const float*)d_in[5];
    const float* W2 = (const float*)d_in[6];
    const float* b2 = (const float*)d_in[7];
    const float* a2 = (const float*)d_in[8];
    float* out = (float*)d_out;

    const int N = in_sizes[0] / DD;   // 50000
    const int E = in_sizes[2];        // 800000

    // ---- CSR + normalization preprocessing (once per call) ----
    k_detect<<<1, 32>>>(ei);
    k_init_node<<<(N + 255) / 256, 256>>>(N);
    k_convert<<<(E + 255) / 256, 256>>>(ei, ew, E);
    k_finalize_deg<<<(N + 255) / 256, 256>>>(N);
    k_scan<<<1, 1024>>>(N);
    k_place<<<(E + 255) / 256, 256>>>(ew, E);

    const int gemm_grid = (N + 63) / 64;
    const int agg_grid  = (N * 32 + 255) / 256;   // warp per node

    // ---- layer 1 ----
    k_gemm<<<gemm_grid, 256>>>(x, W1, 0, N);
    k_aggregate<<<agg_grid, 256>>>(b1, a1, out, 0, N);

    // ---- layer 2 ----
    k_gemm<<<gemm_grid, 256>>>(nullptr, W2, 1, N);
    k_aggregate<<<agg_grid, 256>>>(b2, a2, out, 1, N);
}

// round 6
// speedup vs baseline: 2.3389x; 1.0382x over previous
#include <cuda_runtime.h>

#define NN 50000
#define DD 128
#define EE 800000

// Scratch (__device__ globals; no allocations allowed)
__device__ float g_h    [NN * DD];   // GEMM output
__device__ float g_z    [NN * DD];   // layer-1 activation
__device__ float g_dinv [NN];        // weighted degree -> d^{-1/2}
__device__ int   g_cnt  [NN];        // in-degree counts
__device__ int   g_rowptr[NN + 1];   // CSR row pointers (by dst)
__device__ int   g_cursor[NN];       // placement cursors
__device__ int   g_src  [EE];
__device__ int   g_dst  [EE];
__device__ int   g_esrc [EE];        // CSR-ordered src
__device__ float g_enorm[EE];        // CSR-ordered edge norm
__device__ int   g_is64;             // edge_index dtype flag

// ---------------- init (fused detect + per-node init) ----------------
__global__ void k_init(const int* __restrict__ ei32, int n) {
    int i = blockIdx.x * blockDim.x + threadIdx.x;
    if (i < n) {
        g_dinv[i] = 1.0f;   // self-loop weight
        g_cnt[i]  = 0;
    }
    if (blockIdx.x == 0 && threadIdx.x == 0) {
        // int64 iff odd 32-bit words of first 64 entries are all zero
        int acc = 0;
#pragma unroll
        for (int k = 0; k < 64; ++k) acc |= ei32[2 * k + 1];
        g_is64 = (acc == 0) ? 1 : 0;
    }
}

// ---------------- convert + degree + histogram ----------------
__global__ void k_convert(const int* __restrict__ ei32,
                          const float* __restrict__ ew, int E) {
    int e = blockIdx.x * blockDim.x + threadIdx.x;
    if (e >= E) return;
    int s, d;
    if (g_is64) {
        s = ei32[2 * e];
        d = ei32[2 * (E + e)];
    } else {
        s = ei32[e];
        d = ei32[E + e];
    }
    g_src[e] = s;
    g_dst[e] = d;
    atomicAdd(&g_dinv[d], ew[e]);
    atomicAdd(&g_cnt[d], 1);
}

// ------- single-block warp-shuffle scan (+ fused dinv finalize) -------
__global__ void k_scan(int N) {
    __shared__ int wsum[32];
    __shared__ int carry_s;
    int tid  = threadIdx.x;
    int lane = tid & 31;
    int wid  = tid >> 5;
    if (tid == 0) carry_s = 0;
    __syncthreads();
    for (int base = 0; base < N; base += 1024) {
        int i = base + tid;
        int v = (i < N) ? g_cnt[i] : 0;
        if (i < N) {
            float deg = g_dinv[i];
            g_dinv[i] = (deg > 0.0f) ? rsqrtf(deg) : 0.0f;
        }
        int s = v;
#pragma unroll
        for (int o = 1; o < 32; o <<= 1) {
            int t = __shfl_up_sync(0xFFFFFFFFu, s, o);
            if (lane >= o) s += t;
        }
        if (lane == 31) wsum[wid] = s;
        __syncthreads();
        if (wid == 0) {
            int ws = wsum[lane];
#pragma unroll
            for (int o = 1; o < 32; o <<= 1) {
                int t = __shfl_up_sync(0xFFFFFFFFu, ws, o);
                if (lane >= o) ws += t;
            }
            wsum[lane] = ws;
        }
        __syncthreads();
        int excl = s - v + ((wid > 0) ? wsum[wid - 1] : 0) + carry_s;
        if (i < N) {
            g_rowptr[i] = excl;
            g_cursor[i] = excl;
        }
        __syncthreads();
        if (tid == 0) carry_s += wsum[31];
        __syncthreads();
    }
    if (tid == 0) g_rowptr[N] = carry_s;
}

// -------- place edges into CSR order, compute per-edge norm --------
__global__ void k_place(const float* __restrict__ ew, int E) {
    int e = blockIdx.x * blockDim.x + threadIdx.x;
    if (e >= E) return;
    int s = g_src[e];
    int d = g_dst[e];
    int pos = atomicAdd(&g_cursor[d], 1);
    g_esrc[pos]  = s;
    g_enorm[pos] = g_dinv[s] * ew[e] * g_dinv[d];
}

// ---------------- TF32 helpers ----------------
__device__ __forceinline__ unsigned f2tf32(float f) {
    unsigned u;
    asm("cvt.rna.tf32.f32 %0, %1;" : "=r"(u) : "f"(f));
    return u;
}

#define MMA_TF32(d, a0, a1, a2, a3, b0, b1)                                   \
    asm volatile(                                                             \
        "mma.sync.aligned.m16n8k8.row.col.f32.tf32.tf32.f32 "                 \
        "{%0,%1,%2,%3}, {%4,%5,%6,%7}, {%8,%9}, {%0,%1,%2,%3};"               \
        : "+f"(d[0]), "+f"(d[1]), "+f"(d[2]), "+f"(d[3])                      \
        : "r"(a0), "r"(a1), "r"(a2), "r"(a3), "r"(b0), "r"(b1))

// ------- GEMM: g_h = X @ W via 3xTF32 tensor-core mma -------
// Block: 256 threads (8 warps), tile 128 rows x 128 cols.
// warp_m = warp&3 (32 rows each = 2 m16 tiles), warp_n = warp>>2 (64 cols = 8 n8 tiles)
__global__ void __launch_bounds__(256)
k_gemm(const float* __restrict__ Xext, const float* __restrict__ W,
       int use_gz, int N) {
    __shared__ float xs_hi[128][20], xs_lo[128][20];   // 16 k + pad 4
    __shared__ float ws_hi[16][132], ws_lo[16][132];   // 128 n + pad 4

    const float* __restrict__ X = use_gz ? g_z : Xext;
    int tid  = threadIdx.x;
    int lane = tid & 31;
    int warp = tid >> 5;
    int grp  = lane >> 2;   // 0..7
    int tig  = lane & 3;    // 0..3
    int wm   = warp & 3;    // 32-row tile
    int wn   = warp >> 2;   // 64-col half
    int r0   = blockIdx.x * 128;

    float acc[2][8][4];
#pragma unroll
    for (int mt = 0; mt < 2; ++mt)
#pragma unroll
        for (int nt = 0; nt < 8; ++nt)
#pragma unroll
            for (int c = 0; c < 4; ++c) acc[mt][nt][c] = 0.0f;

    for (int chunk = 0; chunk < 8; ++chunk) {
        int k0 = chunk * 16;
        // load X tile: 128 rows x 16 k = 512 float4
#pragma unroll
        for (int rep = 0; rep < 2; ++rep) {
            int q   = tid + rep * 256;
            int row = q >> 2;
            int qc  = q & 3;
            float4 v = make_float4(0.f, 0.f, 0.f, 0.f);
            if (r0 + row < N)
                v = *(const float4*)&X[(r0 + row) * DD + k0 + qc * 4];
            float e[4] = {v.x, v.y, v.z, v.w};
#pragma unroll
            for (int j = 0; j < 4; ++j) {
                float hi = __uint_as_float(f2tf32(e[j]));
                float lo = __uint_as_float(f2tf32(e[j] - hi));
                xs_hi[row][qc * 4 + j] = hi;
                xs_lo[row][qc * 4 + j] = lo;
            }
        }
        // load W tile: 16 k x 128 n = 512 float4
#pragma unroll
        for (int rep = 0; rep < 2; ++rep) {
            int q  = tid + rep * 256;
            int kk = q >> 5;
            int qc = q & 31;
            float4 v = *(const float4*)&W[(k0 + kk) * DD + qc * 4];
            float e[4] = {v.x, v.y, v.z, v.w};
#pragma unroll
            for (int j = 0; j < 4; ++j) {
                float hi = __uint_as_float(f2tf32(e[j]));
                float lo = __uint_as_float(f2tf32(e[j] - hi));
                ws_hi[kk][qc * 4 + j] = hi;
                ws_lo[kk][qc * 4 + j] = lo;
            }
        }
        __syncthreads();

#pragma unroll
        for (int step = 0; step < 2; ++step) {
            int ks = step * 8;
            unsigned a_hi[2][4], a_lo[2][4];
#pragma unroll
            for (int mt = 0; mt < 2; ++mt) {
                int ar = wm * 32 + mt * 16 + grp;
                a_hi[mt][0] = __float_as_uint(xs_hi[ar    ][ks + tig    ]);
                a_hi[mt][1] = __float_as_uint(xs_hi[ar + 8][ks + tig    ]);
                a_hi[mt][2] = __float_as_uint(xs_hi[ar    ][ks + tig + 4]);
                a_hi[mt][3] = __float_as_uint(xs_hi[ar + 8][ks + tig + 4]);
                a_lo[mt][0] = __float_as_uint(xs_lo[ar    ][ks + tig    ]);
                a_lo[mt][1] = __float_as_uint(xs_lo[ar + 8][ks + tig    ]);
                a_lo[mt][2] = __float_as_uint(xs_lo[ar    ][ks + tig + 4]);
                a_lo[mt][3] = __float_as_uint(xs_lo[ar + 8][ks + tig + 4]);
            }
#pragma unroll
            for (int nt = 0; nt < 8; ++nt) {
                int c0 = wn * 64 + nt * 8 + grp;
                unsigned b_hi0 = __float_as_uint(ws_hi[ks + tig    ][c0]);
                unsigned b_hi1 = __float_as_uint(ws_hi[ks + tig + 4][c0]);
                unsigned b_lo0 = __float_as_uint(ws_lo[ks + tig    ][c0]);
                unsigned b_lo1 = __float_as_uint(ws_lo[ks + tig + 4][c0]);
#pragma unroll
                for (int mt = 0; mt < 2; ++mt) {
                    MMA_TF32(acc[mt][nt], a_hi[mt][0], a_hi[mt][1], a_hi[mt][2], a_hi[mt][3], b_hi0, b_hi1);
                    MMA_TF32(acc[mt][nt], a_hi[mt][0], a_hi[mt][1], a_hi[mt][2], a_hi[mt][3], b_lo0, b_lo1);
                    MMA_TF32(acc[mt][nt], a_lo[mt][0], a_lo[mt][1], a_lo[mt][2], a_lo[mt][3], b_hi0, b_hi1);
                }
            }
        }
        __syncthreads();
    }

    // store accumulators
#pragma unroll
    for (int mt = 0; mt < 2; ++mt) {
#pragma unroll
        for (int nt = 0; nt < 8; ++nt) {
            int row = r0 + wm * 32 + mt * 16 + grp;
            int col = wn * 64 + nt * 8 + 2 * tig;
            if (row < N)
                *(float2*)&g_h[row * DD + col] =
                    make_float2(acc[mt][nt][0], acc[mt][nt][1]);
            if (row + 8 < N)
                *(float2*)&g_h[(row + 8) * DD + col] =
                    make_float2(acc[mt][nt][2], acc[mt][nt][3]);
        }
    }
}

// -------- fused aggregate: warp per node; gather + self-loop + bias + PReLU --------
__global__ void k_aggregate(const float* __restrict__ b,
                            const float* __restrict__ a,
                            float* __restrict__ Oext, int use_ext, int N) {
    int node = (blockIdx.x * blockDim.x + threadIdx.x) >> 5;
    if (node >= N) return;
    int lane = threadIdx.x & 31;

    const float4* __restrict__ h4 = (const float4*)g_h;
    float di  = g_dinv[node];
    float di2 = di * di;

    float4 hv = h4[node * 32 + lane];
    float4 bb = ((const float4*)b)[lane];
    float4 acc;
    acc.x = fmaf(di2, hv.x, bb.x);
    acc.y = fmaf(di2, hv.y, bb.y);
    acc.z = fmaf(di2, hv.z, bb.z);
    acc.w = fmaf(di2, hv.w, bb.w);

    int i   = g_rowptr[node];
    int end = g_rowptr[node + 1];

    for (; i + 4 <= end; i += 4) {
        int   s0 = g_esrc[i],     s1 = g_esrc[i + 1];
        int   s2 = g_esrc[i + 2], s3 = g_esrc[i + 3];
        float w0 = g_enorm[i],     w1 = g_enorm[i + 1];
        float w2 = g_enorm[i + 2], w3 = g_enorm[i + 3];
        float4 v0 = h4[s0 * 32 + lane];
        float4 v1 = h4[s1 * 32 + lane];
        float4 v2 = h4[s2 * 32 + lane];
        float4 v3 = h4[s3 * 32 + lane];
        acc.x = fmaf(w0, v0.x, acc.x); acc.y = fmaf(w0, v0.y, acc.y);
        acc.z = fmaf(w0, v0.z, acc.z); acc.w = fmaf(w0, v0.w, acc.w);
        acc.x = fmaf(w1, v1.x, acc.x); acc.y = fmaf(w1, v1.y, acc.y);
        acc.z = fmaf(w1, v1.z, acc.z); acc.w = fmaf(w1, v1.w, acc.w);
        acc.x = fmaf(w2, v2.x, acc.x); acc.y = fmaf(w2, v2.y, acc.y);
        acc.z = fmaf(w2, v2.z, acc.z); acc.w = fmaf(w2, v2.w, acc.w);
        acc.x = fmaf(w3, v3.x, acc.x); acc.y = fmaf(w3, v3.y, acc.y);
        acc.z = fmaf(w3, v3.z, acc.z); acc.w = fmaf(w3, v3.w, acc.w);
    }
    for (; i < end; ++i) {
        int   s = g_esrc[i];
        float w = g_enorm[i];
        float4 v = h4[s * 32 + lane];
        acc.x = fmaf(w, v.x, acc.x); acc.y = fmaf(w, v.y, acc.y);
        acc.z = fmaf(w, v.z, acc.z); acc.w = fmaf(w, v.w, acc.w);
    }

    float4 aa = ((const float4*)a)[lane];
    acc.x = (acc.x > 0.f) ? acc.x : aa.x * acc.x;
    acc.y = (acc.y > 0.f) ? acc.y : aa.y * acc.y;
    acc.z = (acc.z > 0.f) ? acc.z : aa.z * acc.z;
    acc.w = (acc.w > 0.f) ? acc.w : aa.w * acc.w;

    float4* Z = use_ext ? (float4*)Oext : (float4*)g_z;
    Z[node * 32 + lane] = acc;
}

// -------- launch --------
extern "C" void kernel_launch(void* const* d_in, const int* in_sizes, int n_in,
                              void* d_out, int out_size) {
    const float* x  = (const float*)d_in[0];
    const int*   ei = (const int*)d_in[1];
    const float* ew = (const float*)d_in[2];
    const float* W1 = (const float*)d_in[3];
    const float* b1 = (const float*)d_in[4];
    const float* a1 = (const float*)d_in[5];
    const float* W2 = (const float*)d_in[6];
    const float* b2 = (const float*)d_in[7];
    const float* a2 = (const float*)d_in[8];
    float* out = (float*)d_out;

    const int N = in_sizes[0] / DD;   // 50000
    const int E = in_sizes[2];        // 800000

    // ---- CSR + normalization preprocessing ----
    k_init<<<(N + 255) / 256, 256>>>(ei, N);
    k_convert<<<(E + 255) / 256, 256>>>(ei, ew, E);
    k_scan<<<1, 1024>>>(N);
    k_place<<<(E + 255) / 256, 256>>>(ew, E);

    const int gemm_grid = (N + 127) / 128;        // 391
    const int agg_grid  = (N * 32 + 255) / 256;   // warp per node

    // ---- layer 1 ----
    k_gemm<<<gemm_grid, 256>>>(x, W1, 0, N);
    k_aggregate<<<agg_grid, 256>>>(b1, a1, out, 0, N);

    // ---- layer 2 ----
    k_gemm<<<gemm_grid, 256>>>(nullptr, W2, 1, N);
    k_aggregate<<<agg_grid, 256>>>(b2, a2, out, 1, N);
}

// round 7
// speedup vs baseline: 3.0357x; 1.2979x over previous
#include <cuda_runtime.h>

#define NN 50000
#define DD 128
#define EE 800000
#define NB 49   // ceil(NN/1024)

// Scratch (__device__ globals; no allocations allowed)
__device__ float g_h    [NN * DD];   // GEMM output
__device__ float g_z    [NN * DD];   // layer-1 activation
__device__ float g_dinv [NN];        // weighted degree -> d^{-1/2}
__device__ int   g_cnt  [NN];        // in-degree counts
__device__ int   g_rowptr[NN + 1];   // CSR row pointers (by dst)
__device__ int   g_cursor[NN];       // placement cursors
__device__ int2  g_sd   [EE];        // packed (src, dst)
__device__ int2  g_edge [EE];        // CSR-ordered (src, norm-bits)
__device__ int   g_bsum [64];        // per-block count sums
__device__ int   g_boff [64];        // per-block scan offsets
__device__ int   g_is64;             // edge_index dtype flag
__device__ float g_w1hi[DD * DD], g_w1lo[DD * DD];
__device__ float g_w2hi[DD * DD], g_w2lo[DD * DD];

// ---------------- TF32 helper ----------------
__device__ __forceinline__ unsigned f2tf32(float f) {
    unsigned u;
    asm("cvt.rna.tf32.f32 %0, %1;" : "=r"(u) : "f"(f));
    return u;
}

// ---------------- init (fused detect + per-node init) ----------------
__global__ void k_init(const int* __restrict__ ei32, int n) {
    int i = blockIdx.x * blockDim.x + threadIdx.x;
    if (i < n) {
        g_dinv[i] = 1.0f;   // self-loop weight
        g_cnt[i]  = 0;
    }
    if (blockIdx.x == 0 && threadIdx.x == 0) {
        int acc = 0;
#pragma unroll
        for (int k = 0; k < 64; ++k) acc |= ei32[2 * k + 1];
        g_is64 = (acc == 0) ? 1 : 0;
    }
}

// ---------------- split W1/W2 into tf32 hi/lo ----------------
__global__ void k_splitw(const float* __restrict__ W1,
                         const float* __restrict__ W2) {
    int i = blockIdx.x * blockDim.x + threadIdx.x;
    if (i >= DD * DD) return;
    float w1 = W1[i];
    float h1 = __uint_as_float(f2tf32(w1));
    g_w1hi[i] = h1;
    g_w1lo[i] = __uint_as_float(f2tf32(w1 - h1));
    float w2 = W2[i];
    float h2 = __uint_as_float(f2tf32(w2));
    g_w2hi[i] = h2;
    g_w2lo[i] = __uint_as_float(f2tf32(w2 - h2));
}

// ---------------- convert + degree + histogram ----------------
__global__ void k_convert(const int* __restrict__ ei32,
                          const float* __restrict__ ew, int E) {
    int e = blockIdx.x * blockDim.x + threadIdx.x;
    if (e >= E) return;
    int s, d;
    if (g_is64) {
        s = ei32[2 * e];
        d = ei32[2 * (E + e)];
    } else {
        s = ei32[e];
        d = ei32[E + e];
    }
    g_sd[e] = make_int2(s, d);
    atomicAdd(&g_dinv[d], ew[e]);
    atomicAdd(&g_cnt[d], 1);
}

// ---------------- multi-block scan, stage 1: per-block sums ----------------
__global__ void k_bsum(int N) {
    __shared__ int sh[32];
    int tid  = threadIdx.x;                // 256
    int base = blockIdx.x * 1024;
    int v = 0;
#pragma unroll
    for (int j = 0; j < 4; ++j) {
        int i = base + tid + j * 256;
        v += (i < N) ? g_cnt[i] : 0;
    }
#pragma unroll
    for (int o = 16; o > 0; o >>= 1)
        v += __shfl_down_sync(0xFFFFFFFFu, v, o);
    if ((tid & 31) == 0) sh[tid >> 5] = v;
    __syncthreads();
    if (tid < 8) {
        int t = sh[tid];
#pragma unroll
        for (int o = 4; o > 0; o >>= 1)
            t += __shfl_down_sync(0xFFu, t, o);
        if (tid == 0) g_bsum[blockIdx.x] = t;
    }
}

// ---------------- stage 2: scan the 49 block sums (one tiny block) --------
__global__ void k_bscan(int nb, int N) {
    int tid  = threadIdx.x;                // 64
    int lane = tid & 31;
    int w    = tid >> 5;
    __shared__ int wtot[2];
    int v = (tid < nb) ? g_bsum[tid] : 0;
    int s = v;
#pragma unroll
    for (int o = 1; o < 32; o <<= 1) {
        int t = __shfl_up_sync(0xFFFFFFFFu, s, o);
        if (lane >= o) s += t;
    }
    if (lane == 31) wtot[w] = s;
    __syncthreads();
    int incl = s + ((w == 1) ? wtot[0] : 0);
    if (tid < nb) g_boff[tid] = incl - v;
    if (tid == 63) g_rowptr[N] = wtot[0] + wtot[1];
}

// ------- stage 3: per-tile scan + offset; fused dinv finalize -------
__global__ void k_rowptr(int N) {
    __shared__ int wsum[32];
    int tid  = threadIdx.x;                // 1024
    int lane = tid & 31;
    int wid  = tid >> 5;
    int i = blockIdx.x * 1024 + tid;
    int v = (i < N) ? g_cnt[i] : 0;
    int s = v;
#pragma unroll
    for (int o = 1; o < 32; o <<= 1) {
        int t = __shfl_up_sync(0xFFFFFFFFu, s, o);
        if (lane >= o) s += t;
    }
    if (lane == 31) wsum[wid] = s;
    __syncthreads();
    if (wid == 0) {
        int ws = wsum[lane];
#pragma unroll
        for (int o = 1; o < 32; o <<= 1) {
            int t = __shfl_up_sync(0xFFFFFFFFu, ws, o);
            if (lane >= o) ws += t;
        }
        wsum[lane] = ws;
    }
    __syncthreads();
    int excl = s - v + ((wid > 0) ? wsum[wid - 1] : 0) + g_boff[blockIdx.x];
    if (i < N) {
        g_rowptr[i] = excl;
        g_cursor[i] = excl;
        float deg = g_dinv[i];
        g_dinv[i] = (deg > 0.0f) ? rsqrtf(deg) : 0.0f;
    }
}

// -------- place edges into CSR order with packed (src, norm) record --------
__global__ void k_place(const float* __restrict__ ew, int E) {
    int e = blockIdx.x * blockDim.x + threadIdx.x;
    if (e >= E) return;
    int2 sd = g_sd[e];
    float nrm = g_dinv[sd.x] * ew[e] * g_dinv[sd.y];
    int pos = atomicAdd(&g_cursor[sd.y], 1);
    g_edge[pos] = make_int2(sd.x, __float_as_int(nrm));
}

// ---------------- MMA macro ----------------
#define MMA_TF32(d, a0, a1, a2, a3, b0, b1)                                   \
    asm volatile(                                                             \
        "mma.sync.aligned.m16n8k8.row.col.f32.tf32.tf32.f32 "                 \
        "{%0,%1,%2,%3}, {%4,%5,%6,%7}, {%8,%9}, {%0,%1,%2,%3};"               \
        : "+f"(d[0]), "+f"(d[1]), "+f"(d[2]), "+f"(d[3])                      \
        : "r"(a0), "r"(a1), "r"(a2), "r"(a3), "r"(b0), "r"(b1))

// ------- GEMM: g_h = X @ W via 3xTF32 tensor-core mma -------
__global__ void __launch_bounds__(256)
k_gemm(const float* __restrict__ Xext, int use_gz, int N) {
    __shared__ float xs_hi[128][20], xs_lo[128][20];
    __shared__ float ws_hi[16][132], ws_lo[16][132];

    const float* __restrict__ X   = use_gz ? g_z : Xext;
    const float* __restrict__ Whi = use_gz ? g_w2hi : g_w1hi;
    const float* __restrict__ Wlo = use_gz ? g_w2lo : g_w1lo;

    int tid  = threadIdx.x;
    int lane = tid & 31;
    int warp = tid >> 5;
    int grp  = lane >> 2;
    int tig  = lane & 3;
    int wm   = warp & 3;
    int wn   = warp >> 2;
    int r0   = blockIdx.x * 128;

    float acc[2][8][4];
#pragma unroll
    for (int mt = 0; mt < 2; ++mt)
#pragma unroll
        for (int nt = 0; nt < 8; ++nt)
#pragma unroll
            for (int c = 0; c < 4; ++c) acc[mt][nt][c] = 0.0f;

    for (int chunk = 0; chunk < 8; ++chunk) {
        int k0 = chunk * 16;
        // X tile: 128 rows x 16 k, convert to hi/lo
#pragma unroll
        for (int rep = 0; rep < 2; ++rep) {
            int q   = tid + rep * 256;
            int row = q >> 2;
            int qc  = q & 3;
            float4 v = make_float4(0.f, 0.f, 0.f, 0.f);
            if (r0 + row < N)
                v = *(const float4*)&X[(r0 + row) * DD + k0 + qc * 4];
            float e[4] = {v.x, v.y, v.z, v.w};
#pragma unroll
            for (int j = 0; j < 4; ++j) {
                float hi = __uint_as_float(f2tf32(e[j]));
                xs_hi[row][qc * 4 + j] = hi;
                xs_lo[row][qc * 4 + j] = __uint_as_float(f2tf32(e[j] - hi));
            }
        }
        // W tile: pre-split, plain copies
#pragma unroll
        for (int rep = 0; rep < 2; ++rep) {
            int q  = tid + rep * 256;
            int kk = q >> 5;
            int qc = q & 31;
            *(float4*)&ws_hi[kk][qc * 4] = *(const float4*)&Whi[(k0 + kk) * DD + qc * 4];
            *(float4*)&ws_lo[kk][qc * 4] = *(const float4*)&Wlo[(k0 + kk) * DD + qc * 4];
        }
        __syncthreads();

#pragma unroll
        for (int step = 0; step < 2; ++step) {
            int ks = step * 8;
            unsigned a_hi[2][4], a_lo[2][4];
#pragma unroll
            for (int mt = 0; mt < 2; ++mt) {
                int ar = wm * 32 + mt * 16 + grp;
                a_hi[mt][0] = __float_as_uint(xs_hi[ar    ][ks + tig    ]);
                a_hi[mt][1] = __float_as_uint(xs_hi[ar + 8][ks + tig    ]);
                a_hi[mt][2] = __float_as_uint(xs_hi[ar    ][ks + tig + 4]);
                a_hi[mt][3] = __float_as_uint(xs_hi[ar + 8][ks + tig + 4]);
                a_lo[mt][0] = __float_as_uint(xs_lo[ar    ][ks + tig    ]);
                a_lo[mt][1] = __float_as_uint(xs_lo[ar + 8][ks + tig    ]);
                a_lo[mt][2] = __float_as_uint(xs_lo[ar    ][ks + tig + 4]);
                a_lo[mt][3] = __float_as_uint(xs_lo[ar + 8][ks + tig + 4]);
            }
#pragma unroll
            for (int nt = 0; nt < 8; ++nt) {
                int c0 = wn * 64 + nt * 8 + grp;
                unsigned b_hi0 = __float_as_uint(ws_hi[ks + tig    ][c0]);
                unsigned b_hi1 = __float_as_uint(ws_hi[ks + tig + 4][c0]);
                unsigned b_lo0 = __float_as_uint(ws_lo[ks + tig    ][c0]);
                unsigned b_lo1 = __float_as_uint(ws_lo[ks + tig + 4][c0]);
#pragma unroll
                for (int mt = 0; mt < 2; ++mt) {
                    MMA_TF32(acc[mt][nt], a_hi[mt][0], a_hi[mt][1], a_hi[mt][2], a_hi[mt][3], b_hi0, b_hi1);
                    MMA_TF32(acc[mt][nt], a_hi[mt][0], a_hi[mt][1], a_hi[mt][2], a_hi[mt][3], b_lo0, b_lo1);
                    MMA_TF32(acc[mt][nt], a_lo[mt][0], a_lo[mt][1], a_lo[mt][2], a_lo[mt][3], b_hi0, b_hi1);
                }
            }
        }
        __syncthreads();
    }

#pragma unroll
    for (int mt = 0; mt < 2; ++mt) {
#pragma unroll
        for (int nt = 0; nt < 8; ++nt) {
            int row = r0 + wm * 32 + mt * 16 + grp;
            int col = wn * 64 + nt * 8 + 2 * tig;
            if (row < N)
                *(float2*)&g_h[row * DD + col] = make_float2(acc[mt][nt][0], acc[mt][nt][1]);
            if (row + 8 < N)
                *(float2*)&g_h[(row + 8) * DD + col] = make_float2(acc[mt][nt][2], acc[mt][nt][3]);
        }
    }
}

// -------- fused aggregate: warp per node; gather + self-loop + bias + PReLU --------
__global__ void k_aggregate(const float* __restrict__ b,
                            const float* __restrict__ a,
                            float* __restrict__ Oext, int use_ext, int N) {
    int node = (blockIdx.x * blockDim.x + threadIdx.x) >> 5;
    if (node >= N) return;
    int lane = threadIdx.x & 31;

    const float4* __restrict__ h4 = (const float4*)g_h;
    float di  = g_dinv[node];
    float di2 = di * di;

    float4 hv = h4[node * 32 + lane];
    float4 bb = ((const float4*)b)[lane];
    float4 acc;
    acc.x = fmaf(di2, hv.x, bb.x);
    acc.y = fmaf(di2, hv.y, bb.y);
    acc.z = fmaf(di2, hv.z, bb.z);
    acc.w = fmaf(di2, hv.w, bb.w);

    int i   = g_rowptr[node];
    int end = g_rowptr[node + 1];

    for (; i + 4 <= end; i += 4) {
        int2 e0 = g_edge[i],     e1 = g_edge[i + 1];
        int2 e2 = g_edge[i + 2], e3 = g_edge[i + 3];
        float4 v0 = h4[e0.x * 32 + lane];
        float4 v1 = h4[e1.x * 32 + lane];
        float4 v2 = h4[e2.x * 32 + lane];
        float4 v3 = h4[e3.x * 32 + lane];
        float w0 = __int_as_float(e0.y), w1 = __int_as_float(e1.y);
        float w2 = __int_as_float(e2.y), w3 = __int_as_float(e3.y);
        acc.x = fmaf(w0, v0.x, acc.x); acc.y = fmaf(w0, v0.y, acc.y);
        acc.z = fmaf(w0, v0.z, acc.z); acc.w = fmaf(w0, v0.w, acc.w);
        acc.x = fmaf(w1, v1.x, acc.x); acc.y = fmaf(w1, v1.y, acc.y);
        acc.z = fmaf(w1, v1.z, acc.z); acc.w = fmaf(w1, v1.w, acc.w);
        acc.x = fmaf(w2, v2.x, acc.x); acc.y = fmaf(w2, v2.y, acc.y);
        acc.z = fmaf(w2, v2.z, acc.z); acc.w = fmaf(w2, v2.w, acc.w);
        acc.x = fmaf(w3, v3.x, acc.x); acc.y = fmaf(w3, v3.y, acc.y);
        acc.z = fmaf(w3, v3.z, acc.z); acc.w = fmaf(w3, v3.w, acc.w);
    }
    for (; i < end; ++i) {
        int2 e = g_edge[i];
        float w = __int_as_float(e.y);
        float4 v = h4[e.x * 32 + lane];
        acc.x = fmaf(w, v.x, acc.x); acc.y = fmaf(w, v.y, acc.y);
        acc.z = fmaf(w, v.z, acc.z); acc.w = fmaf(w, v.w, acc.w);
    }

    float4 aa = ((const float4*)a)[lane];
    acc.x = (acc.x > 0.f) ? acc.x : aa.x * acc.x;
    acc.y = (acc.y > 0.f) ? acc.y : aa.y * acc.y;
    acc.z = (acc.z > 0.f) ? acc.z : aa.z * acc.z;
    acc.w = (acc.w > 0.f) ? acc.w : aa.w * acc.w;

    float4* Z = use_ext ? (float4*)Oext : (float4*)g_z;
    Z[node * 32 + lane] = acc;
}

// -------- launch --------
extern "C" void kernel_launch(void* const* d_in, const int* in_sizes, int n_in,
                              void* d_out, int out_size) {
    const float* x  = (const float*)d_in[0];
    const int*   ei = (const int*)d_in[1];
    const float* ew = (const float*)d_in[2];
    const float* W1 = (const float*)d_in[3];
    const float* b1 = (const float*)d_in[4];
    const float* a1 = (const float*)d_in[5];
    const float* W2 = (const float*)d_in[6];
    const float* b2 = (const float*)d_in[7];
    const float* a2 = (const float*)d_in[8];
    float* out = (float*)d_out;

    const int N = in_sizes[0] / DD;   // 50000
    const int E = in_sizes[2];        // 800000
    const int nb = (N + 1023) / 1024; // 49

    // ---- preprocessing ----
    k_init<<<(N + 255) / 256, 256>>>(ei, N);
    k_splitw<<<(DD * DD + 255) / 256, 256>>>(W1, W2);
    k_convert<<<(E + 255) / 256, 256>>>(ei, ew, E);
    k_bsum<<<nb, 256>>>(N);
    k_bscan<<<1, 64>>>(nb, N);
    k_rowptr<<<nb, 1024>>>(N);
    k_place<<<(E + 255) / 256, 256>>>(ew, E);

    const int gemm_grid = (N + 127) / 128;
    const int agg_grid  = (N * 32 + 255) / 256;

    // ---- layer 1 ----
    k_gemm<<<gemm_grid, 256>>>(x, 0, N);
    k_aggregate<<<agg_grid, 256>>>(b1, a1, out, 0, N);

    // ---- layer 2 ----
    k_gemm<<<gemm_grid, 256>>>(nullptr, 1, N);
    k_aggregate<<<agg_grid, 256>>>(b2, a2, out, 1, N);
}

// round 8
// speedup vs baseline: 3.0634x; 1.0091x over previous
#include <cuda_runtime.h>

#define NN 50000
#define DD 128
#define EE 800000
#define NB 49   // ceil(NN/1024)

// Scratch (__device__ globals; no allocations allowed)
__device__ float g_h    [NN * DD];   // GEMM output
__device__ float g_z    [NN * DD];   // layer-1 activation
__device__ float g_dinv [NN];        // weighted degree -> d^{-1/2}
__device__ int   g_cnt  [NN];        // in-degree counts
__device__ int   g_rowptr[NN + 1];   // CSR row pointers (by dst)
__device__ int   g_cursor[NN];       // placement cursors
__device__ int2  g_sd   [EE];        // packed (src, dst)
__device__ int2  g_edge [EE];        // CSR-ordered (src, norm-bits)
__device__ int   g_bsum [64];        // per-block count sums
__device__ int   g_boff [64];        // per-block scan offsets
__device__ int   g_is64;             // edge_index dtype flag
__device__ float g_w1hi[DD * DD], g_w1lo[DD * DD];
__device__ float g_w2hi[DD * DD], g_w2lo[DD * DD];

// ---------------- TF32 helper ----------------
__device__ __forceinline__ unsigned f2tf32(float f) {
    unsigned u;
    asm("cvt.rna.tf32.f32 %0, %1;" : "=r"(u) : "f"(f));
    return u;
}

// ---------------- init (fused detect + per-node init) ----------------
__global__ void k_init(const int* __restrict__ ei32, int n) {
    int i = blockIdx.x * blockDim.x + threadIdx.x;
    if (i < n) {
        g_dinv[i] = 1.0f;   // self-loop weight
        g_cnt[i]  = 0;
    }
    if (blockIdx.x == 0 && threadIdx.x == 0) {
        int acc = 0;
#pragma unroll
        for (int k = 0; k < 64; ++k) acc |= ei32[2 * k + 1];
        g_is64 = (acc == 0) ? 1 : 0;
    }
}

// ---------------- split W1/W2 into tf32 hi/lo ----------------
__global__ void k_splitw(const float* __restrict__ W1,
                         const float* __restrict__ W2) {
    int i = blockIdx.x * blockDim.x + threadIdx.x;
    if (i >= DD * DD) return;
    float w1 = W1[i];
    float h1 = __uint_as_float(f2tf32(w1));
    g_w1hi[i] = h1;
    g_w1lo[i] = __uint_as_float(f2tf32(w1 - h1));
    float w2 = W2[i];
    float h2 = __uint_as_float(f2tf32(w2));
    g_w2hi[i] = h2;
    g_w2lo[i] = __uint_as_float(f2tf32(w2 - h2));
}

// ---------------- convert + degree + histogram ----------------
__global__ void k_convert(const int* __restrict__ ei32,
                          const float* __restrict__ ew, int E) {
    int e = blockIdx.x * blockDim.x + threadIdx.x;
    if (e >= E) return;
    int s, d;
    if (g_is64) {
        s = ei32[2 * e];
        d = ei32[2 * (E + e)];
    } else {
        s = ei32[e];
        d = ei32[E + e];
    }
    g_sd[e] = make_int2(s, d);
    atomicAdd(&g_dinv[d], ew[e]);
    atomicAdd(&g_cnt[d], 1);
}

// ---------------- multi-block scan, stage 1: per-block sums ----------------
__global__ void k_bsum(int N) {
    __shared__ int sh[32];
    int tid  = threadIdx.x;                // 256
    int base = blockIdx.x * 1024;
    int v = 0;
#pragma unroll
    for (int j = 0; j < 4; ++j) {
        int i = base + tid + j * 256;
        v += (i < N) ? g_cnt[i] : 0;
    }
#pragma unroll
    for (int o = 16; o > 0; o >>= 1)
        v += __shfl_down_sync(0xFFFFFFFFu, v, o);
    if ((tid & 31) == 0) sh[tid >> 5] = v;
    __syncthreads();
    if (tid < 8) {
        int t = sh[tid];
#pragma unroll
        for (int o = 4; o > 0; o >>= 1)
            t += __shfl_down_sync(0xFFu, t, o);
        if (tid == 0) g_bsum[blockIdx.x] = t;
    }
}

// ---------------- stage 2: scan the 49 block sums (one tiny block) --------
__global__ void k_bscan(int nb, int N) {
    int tid  = threadIdx.x;                // 64
    int lane = tid & 31;
    int w    = tid >> 5;
    __shared__ int wtot[2];
    int v = (tid < nb) ? g_bsum[tid] : 0;
    int s = v;
#pragma unroll
    for (int o = 1; o < 32; o <<= 1) {
        int t = __shfl_up_sync(0xFFFFFFFFu, s, o);
        if (lane >= o) s += t;
    }
    if (lane == 31) wtot[w] = s;
    __syncthreads();
    int incl = s + ((w == 1) ? wtot[0] : 0);
    if (tid < nb) g_boff[tid] = incl - v;
    if (tid == 63) g_rowptr[N] = wtot[0] + wtot[1];
}

// ------- stage 3: per-tile scan + offset; fused dinv finalize -------
__global__ void k_rowptr(int N) {
    __shared__ int wsum[32];
    int tid  = threadIdx.x;                // 1024
    int lane = tid & 31;
    int wid  = tid >> 5;
    int i = blockIdx.x * 1024 + tid;
    int v = (i < N) ? g_cnt[i] : 0;
    int s = v;
#pragma unroll
    for (int o = 1; o < 32; o <<= 1) {
        int t = __shfl_up_sync(0xFFFFFFFFu, s, o);
        if (lane >= o) s += t;
    }
    if (lane == 31) wsum[wid] = s;
    __syncthreads();
    if (wid == 0) {
        int ws = wsum[lane];
#pragma unroll
        for (int o = 1; o < 32; o <<= 1) {
            int t = __shfl_up_sync(0xFFFFFFFFu, ws, o);
            if (lane >= o) ws += t;
        }
        wsum[lane] = ws;
    }
    __syncthreads();
    int excl = s - v + ((wid > 0) ? wsum[wid - 1] : 0) + g_boff[blockIdx.x];
    if (i < N) {
        g_rowptr[i] = excl;
        g_cursor[i] = excl;
        float deg = g_dinv[i];
        g_dinv[i] = (deg > 0.0f) ? rsqrtf(deg) : 0.0f;
    }
}

// -------- place edges into CSR order with packed (src, norm) record --------
__global__ void k_place(const float* __restrict__ ew, int E) {
    int e = blockIdx.x * blockDim.x + threadIdx.x;
    if (e >= E) return;
    int2 sd = g_sd[e];
    float nrm = g_dinv[sd.x] * ew[e] * g_dinv[sd.y];
    int pos = atomicAdd(&g_cursor[sd.y], 1);
    g_edge[pos] = make_int2(sd.x, __float_as_int(nrm));
}

// ---------------- MMA macro ----------------
#define MMA_TF32(d, a0, a1, a2, a3, b0, b1)                                   \
    asm volatile(                                                             \
        "mma.sync.aligned.m16n8k8.row.col.f32.tf32.tf32.f32 "                 \
        "{%0,%1,%2,%3}, {%4,%5,%6,%7}, {%8,%9}, {%0,%1,%2,%3};"               \
        : "+f"(d[0]), "+f"(d[1]), "+f"(d[2]), "+f"(d[3])                      \
        : "r"(a0), "r"(a1), "r"(a2), "r"(a3), "r"(b0), "r"(b1))

// ------- GEMM: g_h = X @ W via 3xTF32 tensor-core mma -------
__global__ void __launch_bounds__(256)
k_gemm(const float* __restrict__ Xext, int use_gz, int N) {
    __shared__ float xs_hi[128][20], xs_lo[128][20];
    __shared__ float ws_hi[16][132], ws_lo[16][132];

    const float* __restrict__ X   = use_gz ? g_z : Xext;
    const float* __restrict__ Whi = use_gz ? g_w2hi : g_w1hi;
    const float* __restrict__ Wlo = use_gz ? g_w2lo : g_w1lo;

    int tid  = threadIdx.x;
    int lane = tid & 31;
    int warp = tid >> 5;
    int grp  = lane >> 2;
    int tig  = lane & 3;
    int wm   = warp & 3;
    int wn   = warp >> 2;
    int r0   = blockIdx.x * 128;

    float acc[2][8][4];
#pragma unroll
    for (int mt = 0; mt < 2; ++mt)
#pragma unroll
        for (int nt = 0; nt < 8; ++nt)
#pragma unroll
            for (int c = 0; c < 4; ++c) acc[mt][nt][c] = 0.0f;

    for (int chunk = 0; chunk < 8; ++chunk) {
        int k0 = chunk * 16;
        // X tile: 128 rows x 16 k, convert to hi/lo
#pragma unroll
        for (int rep = 0; rep < 2; ++rep) {
            int q   = tid + rep * 256;
            int row = q >> 2;
            int qc  = q & 3;
            float4 v = make_float4(0.f, 0.f, 0.f, 0.f);
            if (r0 + row < N)
                v = *(const float4*)&X[(r0 + row) * DD + k0 + qc * 4];
            float e[4] = {v.x, v.y, v.z, v.w};
#pragma unroll
            for (int j = 0; j < 4; ++j) {
                float hi = __uint_as_float(f2tf32(e[j]));
                xs_hi[row][qc * 4 + j] = hi;
                xs_lo[row][qc * 4 + j] = __uint_as_float(f2tf32(e[j] - hi));
            }
        }
        // W tile: pre-split, plain copies
#pragma unroll
        for (int rep = 0; rep < 2; ++rep) {
            int q  = tid + rep * 256;
            int kk = q >> 5;
            int qc = q & 31;
            *(float4*)&ws_hi[kk][qc * 4] = *(const float4*)&Whi[(k0 + kk) * DD + qc * 4];
            *(float4*)&ws_lo[kk][qc * 4] = *(const float4*)&Wlo[(k0 + kk) * DD + qc * 4];
        }
        __syncthreads();

#pragma unroll
        for (int step = 0; step < 2; ++step) {
            int ks = step * 8;
            unsigned a_hi[2][4], a_lo[2][4];
#pragma unroll
            for (int mt = 0; mt < 2; ++mt) {
                int ar = wm * 32 + mt * 16 + grp;
                a_hi[mt][0] = __float_as_uint(xs_hi[ar    ][ks + tig    ]);
                a_hi[mt][1] = __float_as_uint(xs_hi[ar + 8][ks + tig    ]);
                a_hi[mt][2] = __float_as_uint(xs_hi[ar    ][ks + tig + 4]);
                a_hi[mt][3] = __float_as_uint(xs_hi[ar + 8][ks + tig + 4]);
                a_lo[mt][0] = __float_as_uint(xs_lo[ar    ][ks + tig    ]);
                a_lo[mt][1] = __float_as_uint(xs_lo[ar + 8][ks + tig    ]);
                a_lo[mt][2] = __float_as_uint(xs_lo[ar    ][ks + tig + 4]);
                a_lo[mt][3] = __float_as_uint(xs_lo[ar + 8][ks + tig + 4]);
            }
#pragma unroll
            for (int nt = 0; nt < 8; ++nt) {
                int c0 = wn * 64 + nt * 8 + grp;
                unsigned b_hi0 = __float_as_uint(ws_hi[ks + tig    ][c0]);
                unsigned b_hi1 = __float_as_uint(ws_hi[ks + tig + 4][c0]);
                unsigned b_lo0 = __float_as_uint(ws_lo[ks + tig    ][c0]);
                unsigned b_lo1 = __float_as_uint(ws_lo[ks + tig + 4][c0]);
#pragma unroll
                for (int mt = 0; mt < 2; ++mt) {
                    MMA_TF32(acc[mt][nt], a_hi[mt][0], a_hi[mt][1], a_hi[mt][2], a_hi[mt][3], b_hi0, b_hi1);
                    MMA_TF32(acc[mt][nt], a_hi[mt][0], a_hi[mt][1], a_hi[mt][2], a_hi[mt][3], b_lo0, b_lo1);
                    MMA_TF32(acc[mt][nt], a_lo[mt][0], a_lo[mt][1], a_lo[mt][2], a_lo[mt][3], b_hi0, b_hi1);
                }
            }
        }
        __syncthreads();
    }

#pragma unroll
    for (int mt = 0; mt < 2; ++mt) {
#pragma unroll
        for (int nt = 0; nt < 8; ++nt) {
            int row = r0 + wm * 32 + mt * 16 + grp;
            int col = wn * 64 + nt * 8 + 2 * tig;
            if (row < N)
                *(float2*)&g_h[row * DD + col] = make_float2(acc[mt][nt][0], acc[mt][nt][1]);
            if (row + 8 < N)
                *(float2*)&g_h[(row + 8) * DD + col] = make_float2(acc[mt][nt][2], acc[mt][nt][3]);
        }
    }
}

// -------- fused aggregate: warp per node; gather + self-loop + bias + PReLU --------
__global__ void k_aggregate(const float* __restrict__ b,
                            const float* __restrict__ a,
                            float* __restrict__ Oext, int use_ext, int N) {
    int node = (blockIdx.x * blockDim.x + threadIdx.x) >> 5;
    if (node >= N) return;
    int lane = threadIdx.x & 31;

    const float4* __restrict__ h4 = (const float4*)g_h;
    float di  = g_dinv[node];
    float di2 = di * di;

    float4 hv = h4[node * 32 + lane];
    float4 bb = ((const float4*)b)[lane];
    float4 acc;
    acc.x = fmaf(di2, hv.x, bb.x);
    acc.y = fmaf(di2, hv.y, bb.y);
    acc.z = fmaf(di2, hv.z, bb.z);
    acc.w = fmaf(di2, hv.w, bb.w);

    int i   = g_rowptr[node];
    int end = g_rowptr[node + 1];

    for (; i + 4 <= end; i += 4) {
        int2 e0 = g_edge[i],     e1 = g_edge[i + 1];
        int2 e2 = g_edge[i + 2], e3 = g_edge[i + 3];
        float4 v0 = h4[e0.x * 32 + lane];
        float4 v1 = h4[e1.x * 32 + lane];
        float4 v2 = h4[e2.x * 32 + lane];
        float4 v3 = h4[e3.x * 32 + lane];
        float w0 = __int_as_float(e0.y), w1 = __int_as_float(e1.y);
        float w2 = __int_as_float(e2.y), w3 = __int_as_float(e3.y);
        acc.x = fmaf(w0, v0.x, acc.x); acc.y = fmaf(w0, v0.y, acc.y);
        acc.z = fmaf(w0, v0.z, acc.z); acc.w = fmaf(w0, v0.w, acc.w);
        acc.x = fmaf(w1, v1.x, acc.x); acc.y = fmaf(w1, v1.y, acc.y);
        acc.z = fmaf(w1, v1.z, acc.z); acc.w = fmaf(w1, v1.w, acc.w);
        acc.x = fmaf(w2, v2.x, acc.x); acc.y = fmaf(w2, v2.y, acc.y);
        acc.z = fmaf(w2, v2.z, acc.z); acc.w = fmaf(w2, v2.w, acc.w);
        acc.x = fmaf(w3, v3.x, acc.x); acc.y = fmaf(w3, v3.y, acc.y);
        acc.z = fmaf(w3, v3.z, acc.z); acc.w = fmaf(w3, v3.w, acc.w);
    }
    for (; i < end; ++i) {
        int2 e = g_edge[i];
        float w = __int_as_float(e.y);
        float4 v = h4[e.x * 32 + lane];
        acc.x = fmaf(w, v.x, acc.x); acc.y = fmaf(w, v.y, acc.y);
        acc.z = fmaf(w, v.z, acc.z); acc.w = fmaf(w, v.w, acc.w);
    }

    float4 aa = ((const float4*)a)[lane];
    acc.x = (acc.x > 0.f) ? acc.x : aa.x * acc.x;
    acc.y = (acc.y > 0.f) ? acc.y : aa.y * acc.y;
    acc.z = (acc.z > 0.f) ? acc.z : aa.z * acc.z;
    acc.w = (acc.w > 0.f) ? acc.w : aa.w * acc.w;

    float4* Z = use_ext ? (float4*)Oext : (float4*)g_z;
    Z[node * 32 + lane] = acc;
}

// -------- launch --------
extern "C" void kernel_launch(void* const* d_in, const int* in_sizes, int n_in,
                              void* d_out, int out_size) {
    const float* x  = (const float*)d_in[0];
    const int*   ei = (const int*)d_in[1];
    const float* ew = (const float*)d_in[2];
    const float* W1 = (const float*)d_in[3];
    const float* b1 = (const float*)d_in[4];
    const float* a1 = (const float*)d_in[5];
    const float* W2 = (const float*)d_in[6];
    const float* b2 = (const float*)d_in[7];
    const float* a2 = (const float*)d_in[8];
    float* out = (float*)d_out;

    const int N = in_sizes[0] / DD;   // 50000
    const int E = in_sizes[2];        // 800000
    const int nb = (N + 1023) / 1024; // 49

    // ---- preprocessing ----
    k_init<<<(N + 255) / 256, 256>>>(ei, N);
    k_splitw<<<(DD * DD + 255) / 256, 256>>>(W1, W2);
    k_convert<<<(E + 255) / 256, 256>>>(ei, ew, E);
    k_bsum<<<nb, 256>>>(N);
    k_bscan<<<1, 64>>>(nb, N);
    k_rowptr<<<nb, 1024>>>(N);
    k_place<<<(E + 255) / 256, 256>>>(ew, E);

    const int gemm_grid = (N + 127) / 128;
    const int agg_grid  = (N * 32 + 255) / 256;

    // ---- layer 1 ----
    k_gemm<<<gemm_grid, 256>>>(x, 0, N);
    k_aggregate<<<agg_grid, 256>>>(b1, a1, out, 0, N);

    // ---- layer 2 ----
    k_gemm<<<gemm_grid, 256>>>(nullptr, 1, N);
    k_aggregate<<<agg_grid, 256>>>(b2, a2, out, 1, N);
}